// round 4
// baseline (speedup 1.0000x reference)
#include <cuda_runtime.h>
#include <cuda_bf16.h>

#define FULL_MASK 0xFFFFFFFFu

constexpr int B_ROWS     = 16384;
constexpr int SEQ_L      = 50;
constexpr int N_ITER     = 7;        // 7 * 8 groups = 56 >= 50 positions
constexpr int N_SUBJECTS = 10000;

// Precomputed per-subject exp(score): exp(dot(emb[j], w) + b).
// Softmax without max-subtraction is exact here (scores are O(0.1):
// emb ~ 0.1*N(0,1), w ~ 0.25*N(0,1), D=16 -> no overflow risk in fp32).
__device__ float g_escore[N_SUBJECTS];

__device__ __forceinline__ float dot4(float4 a, float4 b) {
    return a.x * b.x + a.y * b.y + a.z * b.z + a.w * b.w;
}

// ---------------- Prologue: per-subject exp(score) table ----------------
__global__ void __launch_bounds__(256)
escore_kernel(const float* __restrict__ subj_emb,
              const float* __restrict__ attn_w,
              const float* __restrict__ attn_b)
{
    const int j = blockIdx.x * blockDim.x + threadIdx.x;
    if (j >= N_SUBJECTS) return;

    const float4* wp = reinterpret_cast<const float4*>(attn_w);
    const float4 w0 = __ldg(wp + 0), w1 = __ldg(wp + 1),
                 w2 = __ldg(wp + 2), w3 = __ldg(wp + 3);

    const float4* ep = reinterpret_cast<const float4*>(subj_emb) + (size_t)j * 4;
    const float s = dot4(__ldg(ep + 0), w0) + dot4(__ldg(ep + 1), w1)
                  + dot4(__ldg(ep + 2), w2) + dot4(__ldg(ep + 3), w3)
                  + __ldg(attn_b);
    g_escore[j] = __expf(s);
}

// ---------------- Main: warp per row, 8 groups x 4 lanes ----------------
// Group g handles positions p = it*8+g; lane chunk c = lane&3 owns 16B of
// the 64B embedding row, so the 4 lanes of a group hit the same 128B line.
// Per-lane partials: acc = group-partial of pooled chunk c (unnormalized),
// ssum = group-partial softmax denominator (replicated within the group).
__device__ __forceinline__ void pool_fast(
    const int* __restrict__ idx,
    const float4* __restrict__ emb,
    int grp, int chunk,
    float4& acc, float& ssum)
{
    const int i_lo = __ldg(idx + (grp * 4 + chunk));            // = lane
    const int i_hi = (grp * 4 + chunk + 32 < SEQ_L) ? __ldg(idx + grp * 4 + chunk + 32) : 0;

    acc  = make_float4(0.f, 0.f, 0.f, 0.f);
    ssum = 0.f;

    #pragma unroll
    for (int it = 0; it < N_ITER; it++) {
        const int  p   = it * 8 + grp;
        const int  src = (it & 3) * 8 + grp;                    // (it*8+grp)%32
        const int  ind = __shfl_sync(FULL_MASK, (it < 4) ? i_lo : i_hi, src);
        const bool valid = (p < SEQ_L);
        const bool msk   = valid && (ind != 0);

        float4 e = make_float4(0.f, 0.f, 0.f, 0.f);
        if (valid) e = __ldg(emb + (size_t)ind * 4 + chunk);
        // 4 lanes of a group read the same address -> 1 sector, L1-resident.
        const float w = msk ? __ldg(g_escore + ind) : 0.0f;

        ssum += w;
        acc.x = fmaf(w, e.x, acc.x);
        acc.y = fmaf(w, e.y, acc.y);
        acc.z = fmaf(w, e.z, acc.z);
        acc.w = fmaf(w, e.w, acc.w);
    }
}

__global__ void __launch_bounds__(256)
scalar_pooler_kernel(
    const float* __restrict__ subj_emb,
    const float* __restrict__ user_bias,
    const float* __restrict__ item_bias,
    const float* __restrict__ global_bias,
    const int*   __restrict__ user_idx,
    const int*   __restrict__ item_idx,
    const int*   __restrict__ fav,
    const int*   __restrict__ book,
    float*       __restrict__ out)
{
    const int row   = (blockIdx.x * blockDim.x + threadIdx.x) >> 5;
    const int lane  = threadIdx.x & 31;
    const int grp   = lane >> 2;
    const int chunk = lane & 3;
    if (row >= B_ROWS) return;

    const float4* emb = reinterpret_cast<const float4*>(subj_emb);

    float4 au, ai;
    float  su, si;
    pool_fast(fav  + (size_t)row * SEQ_L, emb, grp, chunk, au, su);
    pool_fast(book + (size_t)row * SEQ_L, emb, grp, chunk, ai, si);

    // Reduce denominators across the 8 groups (strides 4,8,16).
    #pragma unroll
    for (int off = 4; off < 32; off <<= 1) {
        su += __shfl_xor_sync(FULL_MASK, su, off);
        si += __shfl_xor_sync(FULL_MASK, si, off);
    }

    // Fully reduce u's chunk across groups; ai stays a per-lane partial.
    #pragma unroll
    for (int off = 4; off < 32; off <<= 1) {
        au.x += __shfl_xor_sync(FULL_MASK, au.x, off);
        au.y += __shfl_xor_sync(FULL_MASK, au.y, off);
        au.z += __shfl_xor_sync(FULL_MASK, au.z, off);
        au.w += __shfl_xor_sync(FULL_MASK, au.w, off);
    }

    // All-pad row: reference pools to the zero row -> inv = 0 matches exactly.
    const float inv_u = (su > 0.f) ? (1.0f / su) : 0.f;
    const float inv_i = (si > 0.f) ? (1.0f / si) : 0.f;

    // dot(u, i): lane contributes dot(u_chunk[c], ai_partial[c, g]); the
    // 32-lane sum counts each (chunk, group) cell exactly once.
    float p = dot4(au, ai);
    #pragma unroll
    for (int off = 16; off; off >>= 1)
        p += __shfl_xor_sync(FULL_MASK, p, off);

    if (lane == 0) {
        out[row] = p * inv_u * inv_i
                 + __ldg(user_bias + __ldg(user_idx + row))
                 + __ldg(item_bias + __ldg(item_idx + row))
                 + __ldg(global_bias);
    }
}

extern "C" void kernel_launch(void* const* d_in, const int* in_sizes, int n_in,
                              void* d_out, int out_size)
{
    const float* subj_emb    = (const float*)d_in[0];
    const float* attn_w      = (const float*)d_in[1];
    const float* attn_b      = (const float*)d_in[2];
    const float* user_bias   = (const float*)d_in[3];
    const float* item_bias   = (const float*)d_in[4];
    const float* global_bias = (const float*)d_in[5];
    const int*   user_idx    = (const int*)d_in[6];
    const int*   item_idx    = (const int*)d_in[7];
    const int*   fav         = (const int*)d_in[8];
    const int*   book        = (const int*)d_in[9];
    float*       out         = (float*)d_out;

    escore_kernel<<<(N_SUBJECTS + 255) / 256, 256>>>(subj_emb, attn_w, attn_b);

    const int threads = 256;                       // 8 warps = 8 rows/block
    const int blocks  = (B_ROWS * 32) / threads;   // 2048
    scalar_pooler_kernel<<<blocks, threads>>>(
        subj_emb, user_bias, item_bias, global_bias,
        user_idx, item_idx, fav, book, out);
}